// round 11
// baseline (speedup 1.0000x reference)
#include <cuda_runtime.h>

#define T_STEPS 750
#define B_TOT   1024
#define HID     100
#define KDIM    104      // 100 recurrent + 4 input-drive rows
#define NTHREADS 128
#define NHEAVY  68       // CTAs with BTILE=4   (68*4 = 272)
#define NLIGHT  376      // CTAs with BTILE=2   (376*2 = 752; 272+752 = 1024)
#define NBLOCKS (NHEAVY + NLIGHT)   // 444 = 148 SMs * 3 -> single wave, 3 warps/SMSP
#define ALPHA   0.01f
#define NSTD    0.1f

__device__ __forceinline__ float tanh_fast(float x) {
    float y;
    asm("tanh.approx.f32 %0, %1;" : "=f"(y) : "f"(x));
    return y;
}
__device__ __forceinline__ unsigned long long pack2(float x) {
    unsigned long long r;
    asm("mov.b64 %0, {%1, %1};" : "=l"(r) : "f"(x));
    return r;
}
__device__ __forceinline__ void ffma2(unsigned long long& d,
                                      unsigned long long a,
                                      unsigned long long b) {
    asm("fma.rn.f32x2 %0, %1, %2, %0;" : "+l"(d) : "l"(a), "l"(b));
}
__device__ __forceinline__ unsigned long long fadd2(unsigned long long a,
                                                    unsigned long long b) {
    unsigned long long r;
    asm("add.rn.f32x2 %0, %1, %2;" : "=l"(r) : "l"(a), "l"(b));
    return r;
}
__device__ __forceinline__ float2 unpack2(unsigned long long v) {
    float2 f;
    asm("mov.b64 {%0, %1}, %2;" : "=f"(f.x), "=f"(f.y) : "l"(v));
    return f;
}

// ---- One RNN step, R5 structure verbatim, parameterized by BT. ----
// BT=4: R row = 16B; per j-pair two LDS.128 (ra = R[j][0..3], rb = R[j+1][0..3]).
// BT=2: R row = 8B; per j-pair ONE LDS.128 covers R[j][0..1] and R[j+1][0..1].
template<int BT>
__device__ __forceinline__ void rnn_step(
    int tcur, int i, int b0,
    float (&x)[BT], const float (&Jreg)[KDIM], float ci,
    const float (&ncur)[BT], float ucur,
    float (&nnext)[BT], float& unext,
    float (&R)[KDIM][BT],
    const float* __restrict__ noise,
    const float* __restrict__ input_seq)
{
    // Phase 1: publish r rows (i<100) + u rows (100..103)
    if (i < HID) {
        if (BT == 4) {
            float4 r0;
            r0.x = tanh_fast(x[0]); r0.y = tanh_fast(x[1]);
            r0.z = tanh_fast(x[2]); r0.w = tanh_fast(x[3]);
            *(float4*)&R[i][0] = r0;
        } else {
            float2 r0;
            r0.x = tanh_fast(x[0]); r0.y = tanh_fast(x[1]);
            *(float2*)&R[i][0] = r0;
        }
    }
    if (i < 4 * BT) R[HID + (i & 3)][i >> 2] = ucur;   // b = i>>2, c = i&3
    __syncthreads();

    // Prefetch next step's noise + input (one full step ahead of use)
    const int tn = (tcur + 1 < T_STEPS) ? (tcur + 1) : tcur;
    {
        const float* np = noise + ((size_t)tn * B_TOT + b0) * HID + i;
#pragma unroll
        for (int b = 0; b < BT; b++)
            nnext[b] = (i < HID) ? np[b * HID] : 0.0f;
        if (i < 4 * BT)
            unext = input_seq[((size_t)tn * B_TOT + b0 + (i >> 2)) * 4 + (i & 3)];
    }

    // Phase 2: y[b] = sum_j Jreg[j] * R[j][b]  (packed, even/odd-j split accs)
    float y[BT];
    if (BT == 4) {
        unsigned long long ya0 = 0ull, ya1 = 0ull, yb0 = 0ull, yb1 = 0ull;
#pragma unroll
        for (int j = 0; j < KDIM; j += 2) {
            ulonglong2 ra = *(const ulonglong2*)&R[j][0];
            ulonglong2 rb = *(const ulonglong2*)&R[j + 1][0];
            unsigned long long ja = pack2(Jreg[j]);
            unsigned long long jb = pack2(Jreg[j + 1]);
            ffma2(ya0, ra.x, ja);
            ffma2(ya1, ra.y, ja);
            ffma2(yb0, rb.x, jb);
            ffma2(yb1, rb.y, jb);
        }
        unsigned long long y01 = fadd2(ya0, yb0);
        unsigned long long y23 = fadd2(ya1, yb1);
        float2 f01 = unpack2(y01), f23 = unpack2(y23);
        y[0] = f01.x; y[1] = f01.y; y[2] = f23.x; y[3] = f23.y;
    } else {
        unsigned long long ya = 0ull, yb = 0ull;
#pragma unroll
        for (int j = 0; j < KDIM; j += 2) {
            // 16B load: (R[j][0], R[j][1], R[j+1][0], R[j+1][1])
            ulonglong2 rr = *(const ulonglong2*)&R[j][0];
            ffma2(ya, rr.x, pack2(Jreg[j]));
            ffma2(yb, rr.y, pack2(Jreg[j + 1]));
        }
        unsigned long long y01 = fadd2(ya, yb);
        float2 f01 = unpack2(y01);
        y[0] = f01.x; y[1] = f01.y;
    }
    __syncthreads();   // all reads of R done before next step overwrites it

    // Phase 3: x <- (1-a)x + a*y + a*c + (a*noise_std)*n
#pragma unroll
    for (int b = 0; b < BT; b++) {
        x[b] = fmaf(1.0f - ALPHA, x[b],
               fmaf(ALPHA, y[b],
               fmaf(ALPHA * NSTD, ncur[b], ci)));
    }
}

// ---- Full per-CTA body (R5 verbatim, templated on BT). ----
template<int BT>
__device__ __forceinline__ void rnn_body(
    int b0,
    const float* __restrict__ input_seq,
    const float* __restrict__ noise,
    const float* __restrict__ J_w,
    const float* __restrict__ Bmat,
    const float* __restrict__ c_x,
    const float* __restrict__ Wout_w,
    const float* __restrict__ Wout_b,
    float* __restrict__ out)
{
    __shared__ __align__(16) float R[KDIM][BT];
    __shared__ float warp_part[4][BT];

    const int i = threadIdx.x;

    float Jreg[KDIM];
#pragma unroll
    for (int j = 0; j < KDIM; j++) {
        float v = 0.0f;
        if (i < HID)
            v = (j < HID) ? J_w[i * HID + j] : Bmat[(j - HID) * HID + i];
        Jreg[j] = v;
    }
    const float ci = (i < HID) ? (ALPHA * c_x[i]) : 0.0f;

    float x[BT];
#pragma unroll
    for (int b = 0; b < BT; b++) x[b] = 0.0f;

    float nA[BT], nB[BT];
    float uA = 0.0f, uB = 0.0f;
    {
        const float* np = noise + (size_t)b0 * HID + i;
#pragma unroll
        for (int b = 0; b < BT; b++)
            nA[b] = (i < HID) ? np[b * HID] : 0.0f;
        if (i < 4 * BT)
            uA = input_seq[((size_t)b0 + (i >> 2)) * 4 + (i & 3)];
    }

    for (int t = 0; t < T_STEPS; t += 2) {
        rnn_step<BT>(t,     i, b0, x, Jreg, ci, nA, uA, nB, uB, R, noise, input_seq);
        rnn_step<BT>(t + 1, i, b0, x, Jreg, ci, nB, uB, nA, uA, R, noise, input_seq);
    }

    // Epilogue: deterministic butterfly + fixed-order cross-warp sum.
    {
        const float w = (i < HID) ? Wout_w[i] : 0.0f;
        float part[BT];
#pragma unroll
        for (int b = 0; b < BT; b++)
            part[b] = (i < HID) ? w * tanhf(x[b]) : 0.0f;
#pragma unroll
        for (int off = 16; off > 0; off >>= 1) {
#pragma unroll
            for (int b = 0; b < BT; b++)
                part[b] += __shfl_xor_sync(0xFFFFFFFFu, part[b], off);
        }
        const int warp = i >> 5;
        if ((i & 31) == 0) {
#pragma unroll
            for (int b = 0; b < BT; b++)
                warp_part[warp][b] = part[b];
        }
        __syncthreads();
        if (i < BT) {
            float s = warp_part[0][i] + warp_part[1][i]
                    + warp_part[2][i] + warp_part[3][i];
            out[b0 + i] = s + Wout_b[0];
        }
    }
}

// Grid 444 = 148*3 (single wave, 3 CTAs/SM): bids 0..67 run BTILE=4,
// bids 68..443 run BTILE=2.  68*4 + 376*2 = 1024.
__global__ void __launch_bounds__(NTHREADS, 3)
rnn_kernel(const float* __restrict__ input_seq,
           const float* __restrict__ noise,
           const float* __restrict__ J_w,
           const float* __restrict__ Bmat,
           const float* __restrict__ c_x,
           const float* __restrict__ Wout_w,
           const float* __restrict__ Wout_b,
           float* __restrict__ out)
{
    const int bid = blockIdx.x;
    if (bid < NHEAVY) {
        rnn_body<4>(bid * 4, input_seq, noise, J_w, Bmat, c_x,
                    Wout_w, Wout_b, out);
    } else {
        rnn_body<2>(NHEAVY * 4 + (bid - NHEAVY) * 2, input_seq, noise, J_w,
                    Bmat, c_x, Wout_w, Wout_b, out);
    }
}

extern "C" void kernel_launch(void* const* d_in, const int* in_sizes, int n_in,
                              void* d_out, int out_size)
{
    const float* input_seq = (const float*)d_in[0];  // [750,1024,4]
    const float* noise     = (const float*)d_in[1];  // [750,1024,100]
    const float* J_w       = (const float*)d_in[2];  // [100,100]
    const float* Bmat      = (const float*)d_in[3];  // [4,100]
    const float* c_x       = (const float*)d_in[4];  // [100]
    const float* Wout_w    = (const float*)d_in[5];  // [1,100]
    const float* Wout_b    = (const float*)d_in[6];  // [1]
    float* out = (float*)d_out;                      // [1024]

    rnn_kernel<<<NBLOCKS, NTHREADS>>>(
        input_seq, noise, J_w, Bmat, c_x, Wout_w, Wout_b, out);
}

// round 12
// speedup vs baseline: 1.1782x; 1.1782x over previous
#include <cuda_runtime.h>

#define T_STEPS 750
#define B_TOT   1024
#define HID     100
#define KDIM    104      // 100 recurrent + 4 input-drive rows
#define KH      52       // K-half length
#define BTILE   4
#define NTHREADS 128
#define NBLOCKS (B_TOT / BTILE)   // 256
#define ALPHA   0.01f
#define NSTD    0.1f

__device__ __forceinline__ float tanh_fast(float x) {
    float y;
    asm("tanh.approx.f32 %0, %1;" : "=f"(y) : "f"(x));
    return y;
}
__device__ __forceinline__ unsigned long long pack2(float x) {
    unsigned long long r;
    asm("mov.b64 %0, {%1, %1};" : "=l"(r) : "f"(x));
    return r;
}
__device__ __forceinline__ void ffma2(unsigned long long& d,
                                      unsigned long long a,
                                      unsigned long long b) {
    asm("fma.rn.f32x2 %0, %1, %2, %0;" : "+l"(d) : "l"(a), "l"(b));
}
__device__ __forceinline__ unsigned long long fadd2(unsigned long long a,
                                                    unsigned long long b) {
    unsigned long long r;
    asm("add.rn.f32x2 %0, %1, %2;" : "=l"(r) : "l"(a), "l"(b));
    return r;
}
__device__ __forceinline__ float2 unpack2(unsigned long long v) {
    float2 f;
    asm("mov.b64 {%0, %1}, %2;" : "=f"(f.x), "=f"(f.y) : "l"(v));
    return f;
}

// Row-paired K-split step.  Thread (h, p), p<KH active:
//   owns output rows (p, p+52) restricted to K-half h (j in [h*52, h*52+52)).
//   One LDS.128 of R[j][0..3] feeds 4 FFMA2 (2 rows x 2 batch-pairs).
// h=1 ships packed partials via Spart on the existing B2 barrier.
__device__ __forceinline__ void rnn_step(
    int tcur, int h, int p, bool act, bool r1s, int r0, int r1,
    int b0, int jbase,
    float (&x0)[BTILE], float (&x1)[BTILE],
    const float (&J0)[KH], const float (&J1)[KH], float ci0, float ci1,
    const float (&n0c)[BTILE], const float (&n1c)[BTILE], float uc,
    float (&n0n)[BTILE], float (&n1n)[BTILE], float& un,
    float (&R)[KDIM][BTILE], unsigned long long (&Spart)[KH][4],
    const float* __restrict__ noise,
    const float* __restrict__ input_seq)
{
    // Phase 1: h=0 publishes r = tanh(x) for its two rows; h=1 publishes u.
    if (h == 0 && act) {
        float4 ra;
        ra.x = tanh_fast(x0[0]); ra.y = tanh_fast(x0[1]);
        ra.z = tanh_fast(x0[2]); ra.w = tanh_fast(x0[3]);
        *(float4*)&R[r0][0] = ra;
        if (r1s) {
            float4 rb;
            rb.x = tanh_fast(x1[0]); rb.y = tanh_fast(x1[1]);
            rb.z = tanh_fast(x1[2]); rb.w = tanh_fast(x1[3]);
            *(float4*)&R[r1][0] = rb;
        }
    }
    if (h == 1 && p < 16) R[HID + (p & 3)][p >> 2] = uc;   // b = p>>2, c = p&3
    __syncthreads();   // B1: R complete (also: Spart reads of t-1 done)

    // Prefetch next step's noise (h=0) + input (h=1) one step ahead.
    const int tn = (tcur + 1 < T_STEPS) ? (tcur + 1) : tcur;
    if (h == 0 && act) {
        const float* np = noise + ((size_t)tn * B_TOT + b0) * HID;
#pragma unroll
        for (int b = 0; b < BTILE; b++)
            n0n[b] = np[b * HID + r0];
#pragma unroll
        for (int b = 0; b < BTILE; b++)
            n1n[b] = r1s ? np[b * HID + r1] : 0.0f;
    }
    if (h == 1 && p < 16)
        un = input_seq[((size_t)tn * B_TOT + b0 + (p >> 2)) * 4 + (p & 3)];

    // Phase 2: partial y over this K-half for BOTH rows.
    // acc00/acc01: row r0 (b01, b23); acc10/acc11: row r1.
    unsigned long long acc00 = 0ull, acc01 = 0ull;
    unsigned long long acc10 = 0ull, acc11 = 0ull;
#pragma unroll
    for (int k = 0; k < KH; k++) {
        ulonglong2 rr = *(const ulonglong2*)&R[jbase + k][0];  // R[j][0..3]
        unsigned long long j0 = pack2(J0[k]);
        unsigned long long j1 = pack2(J1[k]);
        ffma2(acc00, rr.x, j0);
        ffma2(acc01, rr.y, j0);
        ffma2(acc10, rr.x, j1);
        ffma2(acc11, rr.y, j1);
    }

    // h=1 publishes its packed partials.
    if (h == 1 && act) {
        ulonglong2 s0; s0.x = acc00; s0.y = acc01;
        ulonglong2 s1; s1.x = acc10; s1.y = acc11;
        *(ulonglong2*)&Spart[p][0] = s0;
        *(ulonglong2*)&Spart[p][2] = s1;
    }
    __syncthreads();   // B2: partials visible; all R reads complete

    // Phase 3: h=0 combines halves and updates x (registers only).
    if (h == 0 && act) {
        ulonglong2 s0 = *(const ulonglong2*)&Spart[p][0];
        ulonglong2 s1 = *(const ulonglong2*)&Spart[p][2];
        float2 y00 = unpack2(fadd2(acc00, s0.x));
        float2 y01 = unpack2(fadd2(acc01, s0.y));
        float2 y10 = unpack2(fadd2(acc10, s1.x));
        float2 y11 = unpack2(fadd2(acc11, s1.y));
        float y0[BTILE] = { y00.x, y00.y, y01.x, y01.y };
        float y1[BTILE] = { y10.x, y10.y, y11.x, y11.y };
#pragma unroll
        for (int b = 0; b < BTILE; b++) {
            x0[b] = fmaf(1.0f - ALPHA, x0[b],
                    fmaf(ALPHA, y0[b],
                    fmaf(ALPHA * NSTD, n0c[b], ci0)));
            x1[b] = fmaf(1.0f - ALPHA, x1[b],
                    fmaf(ALPHA, y1[b],
                    fmaf(ALPHA * NSTD, n1c[b], ci1)));
        }
    }
}

__global__ void __launch_bounds__(NTHREADS, 2)
rnn_kernel(const float* __restrict__ input_seq,
           const float* __restrict__ noise,
           const float* __restrict__ J_w,
           const float* __restrict__ Bmat,
           const float* __restrict__ c_x,
           const float* __restrict__ Wout_w,
           const float* __restrict__ Wout_b,
           float* __restrict__ out)
{
    __shared__ __align__(16) float R[KDIM][BTILE];
    __shared__ __align__(16) unsigned long long Spart[KH][4];
    __shared__ float warp_part[4][BTILE];

    const int tid = threadIdx.x;
    const int h   = tid >> 6;          // K-half (warps 0-1: h=0, warps 2-3: h=1)
    const int p   = tid & 63;
    const bool act = (p < KH);
    const int r0  = p;                 // first owned row (valid if act)
    const int r1  = p + KH;            // second owned row (52..115)
    const bool r1s = act && (r1 < HID);   // second row is a state row
    const int b0  = blockIdx.x * BTILE;
    const int jbase = h * KH;

    // J rows r0 and r1, restricted to this thread's K-half.
    float J0[KH], J1[KH];
#pragma unroll
    for (int k = 0; k < KH; k++) {
        const int jg = jbase + k;
        float v0 = 0.0f, v1 = 0.0f;
        if (act)
            v0 = (jg < HID) ? J_w[r0 * HID + jg] : Bmat[(jg - HID) * HID + r0];
        if (r1s)
            v1 = (jg < HID) ? J_w[r1 * HID + jg] : Bmat[(jg - HID) * HID + r1];
        J0[k] = v0;
        J1[k] = v1;
    }
    const float ci0 = (h == 0 && act) ? (ALPHA * c_x[r0]) : 0.0f;
    const float ci1 = (h == 0 && r1s) ? (ALPHA * c_x[r1]) : 0.0f;

    float x0[BTILE], x1[BTILE];
#pragma unroll
    for (int b = 0; b < BTILE; b++) { x0[b] = 0.0f; x1[b] = 0.0f; }

    // Prologue: t=0 noise (h=0) and u (h=1) into buffer A.
    float nA0[BTILE], nA1[BTILE], nB0[BTILE], nB1[BTILE];
    float uA = 0.0f, uB = 0.0f;
    if (h == 0 && act) {
        const float* np = noise + (size_t)b0 * HID;
#pragma unroll
        for (int b = 0; b < BTILE; b++) {
            nA0[b] = np[b * HID + r0];
            nA1[b] = r1s ? np[b * HID + r1] : 0.0f;
        }
    }
    if (h == 1 && p < 16)
        uA = input_seq[((size_t)b0 + (p >> 2)) * 4 + (p & 3)];

    // Main scan, unrolled by 2 for noise/input register double-buffering.
    for (int t = 0; t < T_STEPS; t += 2) {
        rnn_step(t,     h, p, act, r1s, r0, r1, b0, jbase,
                 x0, x1, J0, J1, ci0, ci1,
                 nA0, nA1, uA, nB0, nB1, uB,
                 R, Spart, noise, input_seq);
        rnn_step(t + 1, h, p, act, r1s, r0, r1, b0, jbase,
                 x0, x1, J0, J1, ci0, ci1,
                 nB0, nB1, uB, nA0, nA1, uA,
                 R, Spart, noise, input_seq);
    }

    // Epilogue: out[b] = tanh(x_final[b]) . Wout + bias (deterministic:
    // butterfly within warp, fixed-order cross-warp combine; h=1 contributes 0).
    {
        float part[BTILE];
#pragma unroll
        for (int b = 0; b < BTILE; b++) part[b] = 0.0f;
        if (h == 0 && act) {
            const float w0 = Wout_w[r0];
            const float w1 = r1s ? Wout_w[r1] : 0.0f;
#pragma unroll
            for (int b = 0; b < BTILE; b++)
                part[b] = w0 * tanhf(x0[b]) + (r1s ? w1 * tanhf(x1[b]) : 0.0f);
        }
#pragma unroll
        for (int off = 16; off > 0; off >>= 1) {
#pragma unroll
            for (int b = 0; b < BTILE; b++)
                part[b] += __shfl_xor_sync(0xFFFFFFFFu, part[b], off);
        }
        const int warp = tid >> 5;
        if ((tid & 31) == 0) {
#pragma unroll
            for (int b = 0; b < BTILE; b++)
                warp_part[warp][b] = part[b];
        }
        __syncthreads();
        if (tid < BTILE) {
            float s = warp_part[0][tid] + warp_part[1][tid]
                    + warp_part[2][tid] + warp_part[3][tid];
            out[b0 + tid] = s + Wout_b[0];
        }
    }
}

extern "C" void kernel_launch(void* const* d_in, const int* in_sizes, int n_in,
                              void* d_out, int out_size)
{
    const float* input_seq = (const float*)d_in[0];  // [750,1024,4]
    const float* noise     = (const float*)d_in[1];  // [750,1024,100]
    const float* J_w       = (const float*)d_in[2];  // [100,100]
    const float* Bmat      = (const float*)d_in[3];  // [4,100]
    const float* c_x       = (const float*)d_in[4];  // [100]
    const float* Wout_w    = (const float*)d_in[5];  // [1,100]
    const float* Wout_b    = (const float*)d_in[6];  // [1]
    float* out = (float*)d_out;                      // [1024]

    rnn_kernel<<<NBLOCKS, NTHREADS>>>(
        input_seq, noise, J_w, Bmat, c_x, Wout_w, Wout_b, out);
}